// round 16
// baseline (speedup 1.0000x reference)
#include <cuda_runtime.h>
#include <math.h>
#include <stdint.h>

#define KP 32
#define BB 256
#define TT 32
#define DH 128
#define EH 128

typedef unsigned long long ull;

// ---------------- scratch (device globals; no allocation) ----------------
__device__ float g_E1[BB * TT * EH];
__device__ float g_H[2][KP * BB * DH];
__device__ float g_C[2][KP * BB * DH];
__device__ float g_yt[BB];
__device__ float g_spF[BB * DH];
__device__ float g_ctx[BB * EH];
__device__ float g_projP[2][KP * BB];
__device__ float g_pdfP[2][KP * BB];
__device__ int   g_srcH[KP * BB];
__device__ int   g_srcC[KP * BB];
__device__ unsigned g_attnFlag[BB];   // attention done through t+1 (monotonic)
__device__ unsigned g_srcFlag[8];     // resample done through t (monotonic)

__device__ __forceinline__ float sigm(float x) { return 1.0f / (1.0f + expf(-x)); }
__device__ __forceinline__ float softplusf(float x) {
    return fmaxf(x, 0.0f) + log1pf(expf(-fabsf(x)));
}
__device__ __forceinline__ void fma2(ull& d, ull a, ull b) {
    asm("fma.rn.f32x2 %0, %1, %2, %0;" : "+l"(d) : "l"(a), "l"(b));
}
__device__ __forceinline__ float2 unpk(ull v) {
    float2 f; asm("mov.b64 {%0,%1}, %2;" : "=f"(f.x), "=f"(f.y) : "l"(v)); return f;
}
__device__ __forceinline__ ull pk(float lo, float hi) {
    ull u; asm("mov.b64 %0, {%1,%2};" : "=l"(u) : "f"(lo), "f"(hi)); return u;
}
__device__ __forceinline__ uint32_t s2u32(const void* p) {
    uint32_t a;
    asm("{ .reg .u64 t; cvta.to.shared.u64 t, %1; cvt.u32.u64 %0, t; }" : "=r"(a) : "l"(p));
    return a;
}
__device__ __forceinline__ void cp16(uint32_t dst, const void* src) {
    asm volatile("cp.async.ca.shared.global [%0], [%1], 16;" :: "r"(dst), "l"(src));
}
__device__ __forceinline__ void l2pf(const void* p) {
    asm volatile("prefetch.global.L2 [%0];" :: "l"(p));
}
__device__ __forceinline__ void barpair(int id) {
    asm volatile("bar.sync %0, 64;" :: "r"(id) : "memory");
}
#define CP_COMMIT() asm volatile("cp.async.commit_group;")
#define CP_WAIT0()  asm volatile("cp.async.wait_group 0;")

__device__ __forceinline__ void spin_ge(volatile unsigned* f, unsigned tgt) {
    while (*f < tgt) { }
}

// ---------------- smem layouts ---------------------------------------------
struct __align__(16) SmemG {       // GEMM CTA (~48.5 KB) -> 4 CTA/SM
    float ws[2][8 * 256];          // 16 KB : W_hh chunk double buffer (8 rows x 256)
    float h_s[KP * 129];           // 16.5 KB: plain H_{t-1}, padded
    ull   hp[128 * 16];            // 16 KB : k-pair packed (h_2kp, h_2kp+1), j-major
};                                 // G float[32*256] (32 KB) aliases ws+h_s after GEMM
struct __align__(16) SmemT {       // attention CTA (4 batches)
    int   idxH[4][32], idxC[4][32];
    float hb[4][128], cb[4][128], hcp[4][128];
    float a_s[4][32], beta[4][32], ctx[4][128];
    float yt[4];
};
struct __align__(16) SmemR {       // resample CTA
    float proj_s[32][33];
    float pd_s[32][33];
    int   order_s[32][33];
    float lw_s[32][33];
};

// ---------------- K0: E1 precompute (512 CTAs) + flag reset -----------------
__global__ void k0_e1(const float* __restrict__ enc, const float* __restrict__ W1,
                      const float* __restrict__ b1)
{
    int bid = blockIdx.x;
    int b = bid >> 1, th = bid & 1;
    int tid = threadIdx.x;
    __shared__ float enc_s[16 * 128];
    __shared__ float w1_s[16 * 128];
    if (tid == 0 && th == 0) g_attnFlag[b] = 0u;
    if (tid == 1 && th == 0 && b < 8) g_srcFlag[b] = 0u;
    for (int idx = tid; idx < 16 * 128; idx += 256)
        enc_s[idx] = enc[(b * TT + th * 16) * 128 + idx];
    int sub = tid >> 7;
    int h   = tid & 127;
    float acc[8];
#pragma unroll
    for (int i = 0; i < 8; i++) acc[i] = 0.0f;
    for (int ec = 0; ec < 8; ec++) {
        __syncthreads();
        for (int idx = tid; idx < 16 * 128; idx += 256)
            w1_s[idx] = W1[(256 + ec * 16) * 128 + idx];
        __syncthreads();
#pragma unroll 4
        for (int jj = 0; jj < 16; jj++) {
            float wv = w1_s[jj * 128 + h];
            int e = ec * 16 + jj;
#pragma unroll
            for (int i = 0; i < 8; i++)
                acc[i] += enc_s[(sub * 8 + i) * 128 + e] * wv;
        }
    }
    float bv = b1[h];
#pragma unroll
    for (int i = 0; i < 8; i++)
        g_E1[(b * TT + th * 16 + sub * 8 + i) * 128 + h] = acc[i] + bv;
}

// ---------------- kStep: resample(8) + attention(64) + GEMM(512) -----------
// GEMM runs on UNGATHERED H (gather commutes to the epilogue), so GEMM CTAs
// start with zero dependencies; resample gates only attention + epilogues.
__global__ void __launch_bounds__(256, 4) kStep(
        int t, const float* __restrict__ enc, const float* __restrict__ yprev,
        const float* __restrict__ W1, const float* __restrict__ W2,
        const float* __restrict__ b2, const float* __restrict__ fcW,
        const float* __restrict__ fcb, const float* __restrict__ varW,
        const float* __restrict__ varb,
        const float* __restrict__ Whh, const float* __restrict__ Wih,
        const float* __restrict__ bih, const float* __restrict__ bhh,
        const float* __restrict__ eps,
        const float* __restrict__ fcdW, const float* __restrict__ fcdb,
        const float* __restrict__ pdfW, const float* __restrict__ pdfb,
        const float* __restrict__ gumbel)
{
    extern __shared__ char smem_raw[];
    int bid = blockIdx.x;
    int tid = threadIdx.x;
    int rb = (t - 1) & 1, wb = t & 1;

    if (bid < 8) {
        // ===== RESAMPLE CTA: indices for step t, from step t-1 data ==========
        if (t == 0) return;
        SmemR* S = (SmemR*)smem_raw;
        int g = bid;
        int w = tid >> 5, lane = tid & 31;
        float fcdb0 = fcdb[0], pwy = pdfW[128], pb0 = pdfb[0];

#pragma unroll
        for (int m = 0; m < 4; m++) {
            int idx = tid + m * 256;
            int kk = idx >> 5, bb = idx & 31;
            int gi = kk * BB + g * 32 + bb;
            S->proj_s[bb][kk] = g_projP[0][gi] + g_projP[1][gi] + fcdb0;
            S->pd_s[bb][kk]   = g_pdfP[0][gi] + g_pdfP[1][gi];
        }
        __syncthreads();
#pragma unroll
        for (int m = 0; m < 4; m++) {
            int idx = tid + m * 256;
            int bl = idx >> 5, k = idx & 31;
            float v = S->proj_s[bl][k];
            int r = 0;
#pragma unroll
            for (int kp = 0; kp < 32; kp++) {
                float u = S->proj_s[bl][kp];
                r += (u < v) || (u == v && kp < k);
            }
            S->order_s[bl][r] = k;
        }
        __syncthreads();
#pragma unroll
        for (int s = 0; s < 4; s++) {
            int slot = w * 4 + s;
            int bb = lane, bg = g * 32 + bb;
            int k0 = S->order_s[bb][slot];
            float lp = S->pd_s[bb][k0] + g_yt[bg] * pwy + pb0;   // yt of step t-1
            float v = expf(lp);
            float sum = v;
            for (int off = 16; off; off >>= 1) sum += __shfl_xor_sync(0xffffffffu, sum, off);
            S->lw_s[bb][slot] = logf(v / sum + 1e-30f);
        }
        __syncthreads();
#pragma unroll
        for (int pp = 0; pp < 4; pp++) {
            int p = w * 4 + pp;
            for (int it = 0; it < 32; it++) {
                int bg = g * 32 + it;
                float v = S->lw_s[it][lane] +
                          gumbel[(((size_t)(t - 1) * BB + bg) * KP + p) * KP + lane];
                int bi = lane;
                for (int off = 16; off; off >>= 1) {
                    float ov = __shfl_down_sync(0xffffffffu, v, off);
                    int  obi = __shfl_down_sync(0xffffffffu, bi, off);
                    if (ov > v || (ov == v && obi < bi)) { v = ov; bi = obi; }
                }
                if (lane == 0) {
                    g_srcH[p * BB + bg] = S->order_s[it][bi];
                    g_srcC[p * BB + bg] = bi;
                }
            }
        }
        __threadfence();
        __syncthreads();
        if (tid == 0) atomicExch(&g_srcFlag[g], (unsigned)t);
        return;
    }

    if (bid < 72) {
        // ================= ATTENTION CTA (4 batches) =================
        SmemT* S = (SmemT*)smem_raw;
        int abid = bid - 8;
        int grp = tid >> 6, gtid = tid & 63;
        int b = abid * 4 + grp;
        int rgrp = abid >> 3;

        if (t > 0) {
            if (tid == 0) spin_ge(&g_srcFlag[rgrp], (unsigned)t);
            __syncthreads();
            if (tid < 128) {
                int g2 = tid >> 5, p = tid & 31;
                S->idxH[g2][p] = g_srcH[p * BB + abid * 4 + g2];
            } else {
                int g2 = (tid - 128) >> 5, p = tid & 31;
                S->idxC[g2][p] = g_srcC[p * BB + abid * 4 + g2];
            }
        }
        __syncthreads();

#pragma unroll
        for (int half = 0; half < 2; half++) {
            int d = gtid + half * 64;
            float sh = 0.0f, sc = 0.0f;
            if (t > 0) {
#pragma unroll 4
                for (int p = 0; p < KP; p++) {
                    sh += g_H[rb][(S->idxH[grp][p] * BB + b) * DH + d];
                    sc += g_C[rb][(S->idxC[grp][p] * BB + b) * DH + d];
                }
            }
            S->hb[grp][d] = sh * (1.0f / 32.0f);
            S->cb[grp][d] = sc * (1.0f / 32.0f);
        }
        __syncthreads();

#pragma unroll
        for (int half = 0; half < 2; half++) {
            int h = gtid + half * 64;
            float a0 = 0, a1 = 0, a2 = 0, a3 = 0;
            float c0 = 0, c1 = 0, c2 = 0, c3 = 0;
#pragma unroll 4
            for (int j = 0; j < 32; j++) {
                a0 += S->hb[grp][j]      * W1[j * 128 + h];
                a1 += S->hb[grp][j + 32] * W1[(j + 32) * 128 + h];
                a2 += S->hb[grp][j + 64] * W1[(j + 64) * 128 + h];
                a3 += S->hb[grp][j + 96] * W1[(j + 96) * 128 + h];
                c0 += S->cb[grp][j]      * W1[(128 + j) * 128 + h];
                c1 += S->cb[grp][j + 32] * W1[(160 + j) * 128 + h];
                c2 += S->cb[grp][j + 64] * W1[(192 + j) * 128 + h];
                c3 += S->cb[grp][j + 96] * W1[(224 + j) * 128 + h];
            }
            S->hcp[grp][h] = ((a0 + a1) + (a2 + a3)) + ((c0 + c1) + (c2 + c3));
        }
        __syncthreads();

        {
            int w2 = gtid >> 5, lane = gtid & 31;
            for (int q = 0; q < 16; q++) {
                int tp = w2 * 16 + q;
                const float* e1 = &g_E1[(b * TT + tp) * 128];
                float acc = 0.0f;
#pragma unroll
                for (int s = 0; s < 4; s++) {
                    int hh = lane + s * 32;
                    acc += tanhf(S->hcp[grp][hh] + e1[hh]) * W2[hh];
                }
                for (int off = 16; off; off >>= 1)
                    acc += __shfl_down_sync(0xffffffffu, acc, off);
                if (lane == 0) S->a_s[grp][tp] = acc + b2[0];
            }
        }
        __syncthreads();

        if (gtid < 32) {
            float v = S->a_s[grp][gtid];
            float m = v;
            for (int off = 16; off; off >>= 1) m = fmaxf(m, __shfl_xor_sync(0xffffffffu, m, off));
            float e = expf(v - m);
            float s = e;
            for (int off = 16; off; off >>= 1) s += __shfl_xor_sync(0xffffffffu, s, off);
            S->beta[grp][gtid] = e / s;
        }
        __syncthreads();

#pragma unroll
        for (int half = 0; half < 2; half++) {
            int e = gtid + half * 64;
            float a0 = 0, a1 = 0, a2 = 0, a3 = 0;
#pragma unroll 4
            for (int tp = 0; tp < 8; tp++) {
                a0 += S->beta[grp][tp]      * enc[(b * TT + tp) * 128 + e];
                a1 += S->beta[grp][tp + 8]  * enc[(b * TT + tp + 8) * 128 + e];
                a2 += S->beta[grp][tp + 16] * enc[(b * TT + tp + 16) * 128 + e];
                a3 += S->beta[grp][tp + 24] * enc[(b * TT + tp + 24) * 128 + e];
            }
            float acc = (a0 + a1) + (a2 + a3);
            S->ctx[grp][e] = acc;
            g_ctx[b * 128 + e] = acc;
        }
        __syncthreads();

        if (gtid < 32) {
            float acc = 0.0f;
#pragma unroll
            for (int s = 0; s < 4; s++)
                acc += S->ctx[grp][gtid + s * 32] * fcW[gtid + s * 32];
            for (int off = 16; off; off >>= 1)
                acc += __shfl_down_sync(0xffffffffu, acc, off);
            if (gtid == 0) {
                float yt = acc + yprev[b * TT + t] * fcW[128] + fcb[0];
                S->yt[grp] = yt;
                g_yt[b] = yt;   // safe: resample already consumed yt(t-1)
            }
        }
        __syncthreads();

#pragma unroll
        for (int half = 0; half < 2; half++) {
            int d = gtid + half * 64;
            float a0 = 0, a1 = 0, a2 = 0, a3 = 0;
#pragma unroll 4
            for (int j = 0; j < 32; j++) {
                a0 += S->hb[grp][j]      * varW[(1 + j) * 128 + d];
                a1 += S->hb[grp][j + 32] * varW[(33 + j) * 128 + d];
                a2 += S->hb[grp][j + 64] * varW[(65 + j) * 128 + d];
                a3 += S->hb[grp][j + 96] * varW[(97 + j) * 128 + d];
            }
            float v = (a0 + a1) + (a2 + a3) + S->yt[grp] * varW[d] + varb[d];
            g_spF[b * 128 + d] = softplusf(v);
        }
        __threadfence();
        __syncthreads();
        if (tid < 4) atomicExch(&g_attnFlag[abid * 4 + tid], (unsigned)(t + 1));
        return;
    }

    // ===== GEMM CTA: UNGATHERED H, k-pair packed, pairwise W pipeline =====
    SmemG* S = (SmemG*)smem_raw;
    int gb = bid - 72;
    int b = gb >> 1, dh = gb & 1;
    int dhoff = dh * 64;
    int grp = b >> 5;
    int wid = tid >> 5, lane = tid & 31;
    int kh = wid >> 2;           // k-half (0: k<16, 1: k>=16)
    int cg = wid & 3;            // gate (64 cols); pair = warps {cg, cg+4}
    int d0l = lane * 2;
    int d0g = dhoff + d0l;

    // L2 prefetch for epilogue eps rows
    if ((lane & 15) == 0) {
#pragma unroll
        for (int i = 0; i < 4; i++)
            l2pf(&eps[(((size_t)t * KP + wid * 4 + i) * BB + b) * DH + dhoff + (lane >> 4) * 32]);
    }

    ull acc[8][2];               // [kp within half][col 0/1]
#pragma unroll
    for (int i = 0; i < 8; i++) { acc[i][0] = 0ull; acc[i][1] = 0ull; }

    float* Gs = (float*)S;       // alias: G[32][256] over ws+h_s after GEMM

    if (t > 0) {
        // prologue: each pair copies ITS gate segment of chunk 0
        {
            uint32_t dstb = s2u32(&S->ws[0][0]);
#pragma unroll
            for (int n = 0; n < 2; n++) {
                int p = (kh * 32 + lane) + n * 64;
                int row = p >> 4, q = p & 15;
                const float* src = Whh + row * 512 + cg * 128 + dhoff + q * 4;
                cp16(dstb + (row * 256 + cg * 64 + q * 4) * 4, src);
            }
            CP_COMMIT();
        }
        // pass 1: PLAIN h fill (no gather, no dependency on this launch)
        const float* hsrc = g_H[rb];
#pragma unroll
        for (int m = 0; m < 16; m++) {
            int idx = tid + m * 256;
            int k = idx >> 7, j = idx & 127;
            S->h_s[k * 129 + j] = hsrc[(k * BB + b) * DH + j];
        }
        __syncthreads();
        // pass 2: repack to k-pair ulls, j-major
#pragma unroll
        for (int m = 0; m < 8; m++) {
            int idx = tid + m * 256;
            int kp = idx & 15, j = idx >> 4;
            S->hp[j * 16 + kp] = pk(S->h_s[(2 * kp) * 129 + j],
                                    S->h_s[(2 * kp + 1) * 129 + j]);
        }
        __syncthreads();   // hp visible CTA-wide

        // ---- G = H_{t-1} @ W : per-pair pipeline, named barrier only ----
        int barid = cg + 1;
        for (int ch = 0; ch < 16; ch++) {
            CP_WAIT0();
            barpair(barid);
            if (ch + 1 < 16) {
                uint32_t dstb = s2u32(&S->ws[(ch + 1) & 1][0]);
#pragma unroll
                for (int n = 0; n < 2; n++) {
                    int p = (kh * 32 + lane) + n * 64;
                    int row = p >> 4, q = p & 15;
                    const float* src = Whh + ((ch + 1) * 8 + row) * 512 + cg * 128 + dhoff + q * 4;
                    cp16(dstb + (row * 256 + cg * 64 + q * 4) * 4, src);
                }
                CP_COMMIT();
            }
            const float* wsb = S->ws[ch & 1];
#pragma unroll
            for (int jj = 0; jj < 8; jj++) {
                int j = ch * 8 + jj;
                const ull* hpj = &S->hp[j * 16 + kh * 8];
                ulonglong2 hq0 = *(const ulonglong2*)&hpj[0];
                ulonglong2 hq1 = *(const ulonglong2*)&hpj[2];
                ulonglong2 hq2 = *(const ulonglong2*)&hpj[4];
                ulonglong2 hq3 = *(const ulonglong2*)&hpj[6];
                float2 wv = *(const float2*)&wsb[jj * 256 + cg * 64 + d0l];
                ull w0 = pk(wv.x, wv.x);
                ull w1 = pk(wv.y, wv.y);
                fma2(acc[0][0], hq0.x, w0); fma2(acc[0][1], hq0.x, w1);
                fma2(acc[1][0], hq0.y, w0); fma2(acc[1][1], hq0.y, w1);
                fma2(acc[2][0], hq1.x, w0); fma2(acc[2][1], hq1.x, w1);
                fma2(acc[3][0], hq1.y, w0); fma2(acc[3][1], hq1.y, w1);
                fma2(acc[4][0], hq2.x, w0); fma2(acc[4][1], hq2.x, w1);
                fma2(acc[5][0], hq2.y, w0); fma2(acc[5][1], hq2.y, w1);
                fma2(acc[6][0], hq3.x, w0); fma2(acc[6][1], hq3.x, w1);
                fma2(acc[7][0], hq3.y, w0); fma2(acc[7][1], hq3.y, w1);
            }
        }
        __syncthreads();   // ALL pairs done with ws/hp before G alias store

        // store G in UNGATHERED k order (aliases ws+h_s only; hp untouched)
#pragma unroll
        for (int kp = 0; kp < 8; kp++) {
            int k0 = kh * 16 + kp * 2;
            int cc = cg * 64 + d0l;
            float2 v0 = unpk(acc[kp][0]);
            float2 v1 = unpk(acc[kp][1]);
            Gs[k0 * 256 + cc]           = v0.x;
            Gs[(k0 + 1) * 256 + cc]     = v0.y;
            Gs[k0 * 256 + cc + 1]       = v1.x;
            Gs[(k0 + 1) * 256 + cc + 1] = v1.y;
        }
        // no sync here: merged with the post-spin sync below
    }

    // hoist epilogue weight loads above the spin
    float wih[8], bsum[8];
#pragma unroll
    for (int g4 = 0; g4 < 4; g4++)
#pragma unroll
        for (int dd = 0; dd < 2; dd++) {
            int col = g4 * 128 + d0g + dd;
            wih[g4 * 2 + dd]  = Wih[col];
            bsum[g4 * 2 + dd] = bih[col] + bhh[col];
        }
    float fcd0 = fcdW[d0g], fcd1 = fcdW[d0g + 1];
    float pw0 = pdfW[d0g],  pw1 = pdfW[d0g + 1];

    // wait for resample (srcH/srcC) + attention (yt, sp)
    if (tid == 0) {
        if (t > 0) spin_ge(&g_srcFlag[grp], (unsigned)t);
        spin_ge(&g_attnFlag[b], (unsigned)(t + 1));
    }
    __syncthreads();

    // ---- epilogue: gather rows of G via srcH (gather∘GEMM commutation) ----
    float yt = g_yt[b];
    float2 spv = *(const float2*)&g_spF[b * 128 + d0g];
    float xb[8];
#pragma unroll
    for (int c = 0; c < 8; c++) xb[c] = yt * wih[c] + bsum[c];

    float pacc[4], qacc[4];
#pragma unroll
    for (int i = 0; i < 4; i++) {
        int k = wid * 4 + i;
        ull gv[4] = {0ull, 0ull, 0ull, 0ull};
        float cp0 = 0.0f, cp1 = 0.0f;
        if (t > 0) {
            int rowH = g_srcH[k * BB + b];
            int rowC = g_srcC[k * BB + b];
#pragma unroll
            for (int g = 0; g < 4; g++)
                gv[g] = *(const ull*)&Gs[rowH * 256 + g * 64 + d0l];
            float2 cv = *(const float2*)&g_C[rb][(rowC * BB + b) * DH + d0g];
            cp0 = cv.x; cp1 = cv.y;
        }
        float2 gi = unpk(gv[0]);
        float2 gf = unpk(gv[1]);
        float2 gg = unpk(gv[2]);
        float2 go = unpk(gv[3]);
        float ii0 = gi.x + xb[0], ii1 = gi.y + xb[1];
        float ff0 = gf.x + xb[2], ff1 = gf.y + xb[3];
        float gg0 = gg.x + xb[4], gg1 = gg.y + xb[5];
        float oo0 = go.x + xb[6], oo1 = go.y + xb[7];
        float c20 = sigm(ff0) * cp0 + sigm(ii0) * tanhf(gg0);
        float c21 = sigm(ff1) * cp1 + sigm(ii1) * tanhf(gg1);
        float h20 = sigm(oo0) * tanhf(c20);
        float h21 = sigm(oo1) * tanhf(c21);
        float2 ev = *(const float2*)&eps[(((size_t)t * KP + k) * BB + b) * DH + d0g];
        h20 += ev.x * spv.x;
        h21 += ev.y * spv.y;
        int o = (k * BB + b) * DH + d0g;
        *(float2*)&g_H[wb][o] = make_float2(h20, h21);
        *(float2*)&g_C[wb][o] = make_float2(c20, c21);
        pacc[i] = h20 * fcd0 + h21 * fcd1;
        qacc[i] = h20 * pw0 + h21 * pw1;
    }
#pragma unroll
    for (int i = 0; i < 4; i++) {
        float p = pacc[i], q = qacc[i];
        for (int off = 16; off; off >>= 1) {
            p += __shfl_down_sync(0xffffffffu, p, off);
            q += __shfl_down_sync(0xffffffffu, q, off);
        }
        if (lane == 0) {
            int k = wid * 4 + i;
            g_projP[dh][k * BB + b] = p;
            g_pdfP[dh][k * BB + b] = q;
        }
    }
}

// ---------------- K3: final resample (for k4) ------------------------------
__global__ void __launch_bounds__(1024) k3_resample(
        int t, const float* __restrict__ gumbel,
        const float* __restrict__ pdfW, const float* __restrict__ pdfb,
        const float* __restrict__ fcdb)
{
    int blk = blockIdx.x;
    int tid = threadIdx.x;
    __shared__ float proj_s[32][33];
    __shared__ int   order_s[32][33];
    __shared__ float pd_s[32][33];
    __shared__ float lw_s[32][33];

    {
        int kk = tid >> 5, bb = tid & 31;
        int gi = kk * BB + blk * 32 + bb;
        proj_s[bb][kk] = g_projP[0][gi] + g_projP[1][gi] + fcdb[0];
        pd_s[bb][kk]   = g_pdfP[0][gi] + g_pdfP[1][gi];
    }
    __syncthreads();
    {
        int bl = tid >> 5, k = tid & 31;
        float v = proj_s[bl][k];
        int r = 0;
#pragma unroll
        for (int kp = 0; kp < 32; kp++) {
            float u = proj_s[bl][kp];
            r += (u < v) || (u == v && kp < k);
        }
        order_s[bl][r] = k;
    }
    __syncthreads();
    {
        int slot = tid >> 5, bb = tid & 31;
        int bg = blk * 32 + bb;
        int k0 = order_s[bb][slot];
        float lp = pd_s[bb][k0] + g_yt[bg] * pdfW[128] + pdfb[0];
        float v = expf(lp);
        float s = v;
        for (int off = 16; off; off >>= 1) s += __shfl_xor_sync(0xffffffffu, s, off);
        lw_s[bb][slot] = logf(v / s + 1e-30f);
    }
    __syncthreads();
    {
        int p = tid >> 5, lane = tid & 31;
        const float* gbase = &gumbel[(((size_t)t * BB + blk * 32) * KP + p) * KP + lane];
        float gv[32];
#pragma unroll
        for (int it = 0; it < 32; it++)
            gv[it] = gbase[(size_t)it * KP * KP];
#pragma unroll
        for (int it = 0; it < 32; it++) {
            float v = lw_s[it][lane] + gv[it];
            int bi = lane;
            for (int off = 16; off; off >>= 1) {
                float ov = __shfl_down_sync(0xffffffffu, v, off);
                int  obi = __shfl_down_sync(0xffffffffu, bi, off);
                if (ov > v || (ov == v && obi < bi)) { v = ov; bi = obi; }
            }
            if (lane == 0) {
                int bg = blk * 32 + it;
                g_srcH[p * BB + bg] = order_s[it][bi];
                g_srcC[p * BB + bg] = bi;
            }
        }
    }
}

// ---------------- K4: final projections -----------------------------------
__global__ void k4_out(const float* __restrict__ fcdW, const float* __restrict__ fcdb,
                       const float* __restrict__ fceW, const float* __restrict__ fceb,
                       float* __restrict__ out)
{
    int b = blockIdx.x * 8 + (threadIdx.x >> 5);
    int lane = threadIdx.x & 31;
    float a1 = 0.0f, a2 = 0.0f;
    for (int d = lane; d < 128; d += 32) {
        float hm = 0.0f;
        for (int p = 0; p < KP; p++) {
            int row = g_srcH[p * BB + b];
            hm += g_H[1][(row * BB + b) * DH + d];   // (T-1)&1 == 1
        }
        a1 += (hm * (1.0f / 32.0f)) * fcdW[d];
        a2 += g_ctx[b * 128 + d] * fceW[d];
    }
    for (int off = 16; off; off >>= 1) {
        a1 += __shfl_down_sync(0xffffffffu, a1, off);
        a2 += __shfl_down_sync(0xffffffffu, a2, off);
    }
    if (lane == 0) out[b] = a1 + fcdb[0] + a2 + fceb[0];
}

// ---------------- launch ---------------------------------------------------
extern "C" void kernel_launch(void* const* d_in, const int* in_sizes, int n_in,
                              void* d_out, int out_size)
{
    const float* enc   = (const float*)d_in[0];
    const float* yprev = (const float*)d_in[1];
    const float* eps   = (const float*)d_in[2];
    const float* gum   = (const float*)d_in[3];
    const float* W1    = (const float*)d_in[4];
    const float* b1    = (const float*)d_in[5];
    const float* W2    = (const float*)d_in[6];
    const float* b2    = (const float*)d_in[7];
    const float* Wih   = (const float*)d_in[8];
    const float* Whh   = (const float*)d_in[9];
    const float* bih   = (const float*)d_in[10];
    const float* bhh   = (const float*)d_in[11];
    const float* fcW   = (const float*)d_in[12];
    const float* fcb   = (const float*)d_in[13];
    const float* fcdW  = (const float*)d_in[14];
    const float* fcdb  = (const float*)d_in[15];
    const float* fceW  = (const float*)d_in[16];
    const float* fceb  = (const float*)d_in[17];
    const float* varW  = (const float*)d_in[18];
    const float* varb  = (const float*)d_in[19];
    const float* pdfW  = (const float*)d_in[20];
    const float* pdfb  = (const float*)d_in[21];
    float* out = (float*)d_out;

    int smem = (int)sizeof(SmemG);
    if ((int)sizeof(SmemT) > smem) smem = (int)sizeof(SmemT);
    if ((int)sizeof(SmemR) > smem) smem = (int)sizeof(SmemR);
    cudaFuncSetAttribute(kStep, cudaFuncAttributeMaxDynamicSharedMemorySize, smem);

    k0_e1<<<BB * 2, 256>>>(enc, W1, b1);
    for (int t = 0; t < TT; t++) {
        kStep<<<8 + 64 + BB * 2, 256, smem>>>(t, enc, yprev, W1, W2, b2, fcW, fcb,
                                              varW, varb, Whh, Wih, bih, bhh, eps,
                                              fcdW, fcdb, pdfW, pdfb, gum);
    }
    k3_resample<<<8, 1024>>>(TT - 1, gum, pdfW, pdfb, fcdb);
    k4_out<<<BB / 8, 256>>>(fcdW, fcdb, fceW, fceb, out);
}

// round 17
// speedup vs baseline: 1.6432x; 1.6432x over previous
#include <cuda_runtime.h>
#include <math.h>
#include <stdint.h>

#define KP 32
#define BB 256
#define TT 32
#define DH 128
#define EH 128

typedef unsigned long long ull;

// ---------------- scratch (device globals; no allocation) ----------------
__device__ float g_E1[BB * TT * EH];
__device__ float g_H[2][KP * BB * DH];
__device__ float g_C[2][KP * BB * DH];
__device__ float g_yt[BB];
__device__ float g_spF[BB * DH];
__device__ float g_ctx[BB * EH];
__device__ float g_projP[2][KP * BB];
__device__ float g_pdfP[2][KP * BB];
__device__ int   g_srcH[KP * BB];
__device__ int   g_srcC[KP * BB];
__device__ unsigned g_attnFlag[BB];   // attention done through t+1 (monotonic)

__device__ __forceinline__ float sigm(float x) { return 1.0f / (1.0f + expf(-x)); }
__device__ __forceinline__ float softplusf(float x) {
    return fmaxf(x, 0.0f) + log1pf(expf(-fabsf(x)));
}
__device__ __forceinline__ void fma2(ull& d, ull a, ull b) {
    asm("fma.rn.f32x2 %0, %1, %2, %0;" : "+l"(d) : "l"(a), "l"(b));
}
__device__ __forceinline__ float2 unpk(ull v) {
    float2 f; asm("mov.b64 {%0,%1}, %2;" : "=f"(f.x), "=f"(f.y) : "l"(v)); return f;
}
__device__ __forceinline__ ull pk(float lo, float hi) {
    ull u; asm("mov.b64 %0, {%1,%2};" : "=l"(u) : "f"(lo), "f"(hi)); return u;
}
__device__ __forceinline__ uint32_t s2u32(const void* p) {
    uint32_t a;
    asm("{ .reg .u64 t; cvta.to.shared.u64 t, %1; cvt.u32.u64 %0, t; }" : "=r"(a) : "l"(p));
    return a;
}
__device__ __forceinline__ void cp16(uint32_t dst, const void* src) {
    asm volatile("cp.async.ca.shared.global [%0], [%1], 16;" :: "r"(dst), "l"(src));
}
__device__ __forceinline__ void l2pf(const void* p) {
    asm volatile("prefetch.global.L2 [%0];" :: "l"(p));
}
__device__ __forceinline__ void barpair(int id) {
    asm volatile("bar.sync %0, 64;" :: "r"(id) : "memory");
}
#define CP_COMMIT() asm volatile("cp.async.commit_group;")
#define CP_WAIT0()  asm volatile("cp.async.wait_group 0;")

__device__ __forceinline__ void spin_ge(volatile unsigned* f, unsigned tgt) {
    while (*f < tgt) { }
}

// ---------------- smem layouts ---------------------------------------------
struct __align__(16) SmemG {       // GEMM CTA (~34 KB) -> 4 CTA/SM
    float ws[2][8 * 256];          // 16 KB : W_hh chunk double buffer (8 rows x 256)
    ull   hp[128 * 18];            // 18 KB : k-pair packed (h_2kp, h_2kp+1), j-major, pad 18
};                                 // G float[32*256] (32 KB) aliases ws+hp[0..] after GEMM
struct __align__(16) SmemT {       // attention CTA (4 batches)
    int   idxH[4][32], idxC[4][32];
    float hb[4][128], cb[4][128], hcp[4][128];
    float a_s[4][32], beta[4][32], ctx[4][128];
    float yt[4];
};

// ---------------- K0: E1 precompute (512 CTAs) + flag reset -----------------
__global__ void k0_e1(const float* __restrict__ enc, const float* __restrict__ W1,
                      const float* __restrict__ b1)
{
    int bid = blockIdx.x;
    int b = bid >> 1, th = bid & 1;     // t-half: rows th*16 .. th*16+15
    int tid = threadIdx.x;
    __shared__ float enc_s[16 * 128];
    __shared__ float w1_s[16 * 128];
    if (tid == 0 && th == 0) g_attnFlag[b] = 0u;
    for (int idx = tid; idx < 16 * 128; idx += 256)
        enc_s[idx] = enc[(b * TT + th * 16) * 128 + idx];
    int sub = tid >> 7;                 // 0..1 : 8 t' each
    int h   = tid & 127;
    float acc[8];
#pragma unroll
    for (int i = 0; i < 8; i++) acc[i] = 0.0f;
    for (int ec = 0; ec < 8; ec++) {
        __syncthreads();
        for (int idx = tid; idx < 16 * 128; idx += 256)
            w1_s[idx] = W1[(256 + ec * 16) * 128 + idx];
        __syncthreads();
#pragma unroll 4
        for (int jj = 0; jj < 16; jj++) {
            float wv = w1_s[jj * 128 + h];
            int e = ec * 16 + jj;
#pragma unroll
            for (int i = 0; i < 8; i++)
                acc[i] += enc_s[(sub * 8 + i) * 128 + e] * wv;
        }
    }
    float bv = b1[h];
#pragma unroll
    for (int i = 0; i < 8; i++)
        g_E1[(b * TT + th * 16 + sub * 8 + i) * 128 + h] = acc[i] + bv;
}

// ---------------- kStep: attention(64) + GEMM(512) CTAs --------------------
__global__ void __launch_bounds__(256, 4) kStep(
        int t, const float* __restrict__ enc, const float* __restrict__ yprev,
        const float* __restrict__ W1, const float* __restrict__ W2,
        const float* __restrict__ b2, const float* __restrict__ fcW,
        const float* __restrict__ fcb, const float* __restrict__ varW,
        const float* __restrict__ varb,
        const float* __restrict__ Whh, const float* __restrict__ Wih,
        const float* __restrict__ bih, const float* __restrict__ bhh,
        const float* __restrict__ eps,
        const float* __restrict__ fcdW, const float* __restrict__ pdfW)
{
    extern __shared__ char smem_raw[];
    int bid = blockIdx.x;
    int tid = threadIdx.x;
    int rb = (t - 1) & 1, wb = t & 1;

    if (bid < 64) {
        // ================= ATTENTION CTA (4 batches) =================
        SmemT* S = (SmemT*)smem_raw;
        int abid = bid;
        int grp = tid >> 6, gtid = tid & 63;
        int b = abid * 4 + grp;

        if (t > 0) {
            if (tid < 128) {
                int g2 = tid >> 5, p = tid & 31;
                S->idxH[g2][p] = g_srcH[p * BB + abid * 4 + g2];
            } else {
                int g2 = (tid - 128) >> 5, p = tid & 31;
                S->idxC[g2][p] = g_srcC[p * BB + abid * 4 + g2];
            }
        }
        __syncthreads();

#pragma unroll
        for (int half = 0; half < 2; half++) {
            int d = gtid + half * 64;
            float sh = 0.0f, sc = 0.0f;
            if (t > 0) {
#pragma unroll 4
                for (int p = 0; p < KP; p++) {
                    sh += g_H[rb][(S->idxH[grp][p] * BB + b) * DH + d];
                    sc += g_C[rb][(S->idxC[grp][p] * BB + b) * DH + d];
                }
            }
            S->hb[grp][d] = sh * (1.0f / 32.0f);
            S->cb[grp][d] = sc * (1.0f / 32.0f);
        }
        __syncthreads();

#pragma unroll
        for (int half = 0; half < 2; half++) {
            int h = gtid + half * 64;
            float a0 = 0, a1 = 0, a2 = 0, a3 = 0;
            float c0 = 0, c1 = 0, c2 = 0, c3 = 0;
#pragma unroll 4
            for (int j = 0; j < 32; j++) {
                a0 += S->hb[grp][j]      * W1[j * 128 + h];
                a1 += S->hb[grp][j + 32] * W1[(j + 32) * 128 + h];
                a2 += S->hb[grp][j + 64] * W1[(j + 64) * 128 + h];
                a3 += S->hb[grp][j + 96] * W1[(j + 96) * 128 + h];
                c0 += S->cb[grp][j]      * W1[(128 + j) * 128 + h];
                c1 += S->cb[grp][j + 32] * W1[(160 + j) * 128 + h];
                c2 += S->cb[grp][j + 64] * W1[(192 + j) * 128 + h];
                c3 += S->cb[grp][j + 96] * W1[(224 + j) * 128 + h];
            }
            S->hcp[grp][h] = ((a0 + a1) + (a2 + a3)) + ((c0 + c1) + (c2 + c3));
        }
        __syncthreads();

        {
            int w2 = gtid >> 5, lane = gtid & 31;
            for (int q = 0; q < 16; q++) {
                int tp = w2 * 16 + q;
                const float* e1 = &g_E1[(b * TT + tp) * 128];
                float acc = 0.0f;
#pragma unroll
                for (int s = 0; s < 4; s++) {
                    int hh = lane + s * 32;
                    acc += tanhf(S->hcp[grp][hh] + e1[hh]) * W2[hh];
                }
                for (int off = 16; off; off >>= 1)
                    acc += __shfl_down_sync(0xffffffffu, acc, off);
                if (lane == 0) S->a_s[grp][tp] = acc + b2[0];
            }
        }
        __syncthreads();

        if (gtid < 32) {
            float v = S->a_s[grp][gtid];
            float m = v;
            for (int off = 16; off; off >>= 1) m = fmaxf(m, __shfl_xor_sync(0xffffffffu, m, off));
            float e = expf(v - m);
            float s = e;
            for (int off = 16; off; off >>= 1) s += __shfl_xor_sync(0xffffffffu, s, off);
            S->beta[grp][gtid] = e / s;
        }
        __syncthreads();

#pragma unroll
        for (int half = 0; half < 2; half++) {
            int e = gtid + half * 64;
            float a0 = 0, a1 = 0, a2 = 0, a3 = 0;
#pragma unroll 4
            for (int tp = 0; tp < 8; tp++) {
                a0 += S->beta[grp][tp]      * enc[(b * TT + tp) * 128 + e];
                a1 += S->beta[grp][tp + 8]  * enc[(b * TT + tp + 8) * 128 + e];
                a2 += S->beta[grp][tp + 16] * enc[(b * TT + tp + 16) * 128 + e];
                a3 += S->beta[grp][tp + 24] * enc[(b * TT + tp + 24) * 128 + e];
            }
            float acc = (a0 + a1) + (a2 + a3);
            S->ctx[grp][e] = acc;
            g_ctx[b * 128 + e] = acc;
        }
        __syncthreads();

        if (gtid < 32) {
            float acc = 0.0f;
#pragma unroll
            for (int s = 0; s < 4; s++)
                acc += S->ctx[grp][gtid + s * 32] * fcW[gtid + s * 32];
            for (int off = 16; off; off >>= 1)
                acc += __shfl_down_sync(0xffffffffu, acc, off);
            if (gtid == 0) {
                float yt = acc + yprev[b * TT + t] * fcW[128] + fcb[0];
                S->yt[grp] = yt;
                g_yt[b] = yt;
            }
        }
        __syncthreads();

#pragma unroll
        for (int half = 0; half < 2; half++) {
            int d = gtid + half * 64;
            float a0 = 0, a1 = 0, a2 = 0, a3 = 0;
#pragma unroll 4
            for (int j = 0; j < 32; j++) {
                a0 += S->hb[grp][j]      * varW[(1 + j) * 128 + d];
                a1 += S->hb[grp][j + 32] * varW[(33 + j) * 128 + d];
                a2 += S->hb[grp][j + 64] * varW[(65 + j) * 128 + d];
                a3 += S->hb[grp][j + 96] * varW[(97 + j) * 128 + d];
            }
            float v = (a0 + a1) + (a2 + a3) + S->yt[grp] * varW[d] + varb[d];
            g_spF[b * 128 + d] = softplusf(v);
        }
        __threadfence();
        __syncthreads();
        if (tid < 4) atomicExch(&g_attnFlag[abid * 4 + tid], (unsigned)(t + 1));
        return;
    }

    // ===== GEMM CTA: k-pair packed, direct gather-pack, pairwise W pipeline =====
    SmemG* S = (SmemG*)smem_raw;
    int gb = bid - 64;
    int b = gb >> 1, dh = gb & 1;
    int dhoff = dh * 64;
    int wid = tid >> 5, lane = tid & 31;
    int kh = wid >> 2;           // k-half (0: k<16, 1: k>=16)
    int cg = wid & 3;            // gate (64 cols); pair = warps {cg, cg+4}
    int d0l = lane * 2;
    int d0g = dhoff + d0l;

    // L2 prefetch for epilogue eps rows
    if ((lane & 15) == 0) {
#pragma unroll
        for (int i = 0; i < 4; i++)
            l2pf(&eps[(((size_t)t * KP + wid * 4 + i) * BB + b) * DH + dhoff + (lane >> 4) * 32]);
    }

    ull acc[8][2];               // [kp within half][col 0/1]
#pragma unroll
    for (int i = 0; i < 8; i++) { acc[i][0] = 0ull; acc[i][1] = 0ull; }

    float* Gs = (float*)S;       // alias: G[32][256] over ws+hp after GEMM

    if (t > 0) {
        // prologue: each pair copies ITS gate segment of chunk 0 (2 cp16/thread)
        {
            uint32_t dstb = s2u32(&S->ws[0][0]);
#pragma unroll
            for (int n = 0; n < 2; n++) {
                int p = (kh * 32 + lane) + n * 64;   // 0..127 within segment
                int row = p >> 4, q = p & 15;
                const float* src = Whh + row * 512 + cg * 128 + dhoff + q * 4;
                cp16(dstb + (row * 256 + cg * 64 + q * 4) * 4, src);
            }
            CP_COMMIT();
        }
        // direct gather-pack: hp[j*18+kp] = (h[2kp][j], h[2kp+1][j]) gathered
        // srcH loads are warp-uniform (kp fixed per 128-thread span); h loads
        // coalesced over j; STS 4-way conflict via pad-18 (benign).
        const float* hsrc = g_H[rb];
#pragma unroll
        for (int m = 0; m < 8; m++) {
            int idx = tid + m * 256;       // 0..2047
            int j = idx & 127, kp = idx >> 7;   // kp 0..15
            int r0 = g_srcH[(2 * kp) * BB + b];
            int r1 = g_srcH[(2 * kp + 1) * BB + b];
            S->hp[j * 18 + kp] = pk(hsrc[(r0 * BB + b) * DH + j],
                                    hsrc[(r1 * BB + b) * DH + j]);
        }
        __syncthreads();   // hp visible CTA-wide before any warp reads it

        // ---- G = gathered-H @ W : per-pair pipeline, named barrier only ----
        int barid = cg + 1;
        for (int ch = 0; ch < 16; ch++) {
            CP_WAIT0();          // own copies of chunk ch's segment landed
            barpair(barid);      // pair: copies visible + both done with ch-1
            if (ch + 1 < 16) {   // copy next chunk's segment into other buffer
                uint32_t dstb = s2u32(&S->ws[(ch + 1) & 1][0]);
#pragma unroll
                for (int n = 0; n < 2; n++) {
                    int p = (kh * 32 + lane) + n * 64;
                    int row = p >> 4, q = p & 15;
                    const float* src = Whh + ((ch + 1) * 8 + row) * 512 + cg * 128 + dhoff + q * 4;
                    cp16(dstb + (row * 256 + cg * 64 + q * 4) * 4, src);
                }
                CP_COMMIT();
            }
            const float* wsb = S->ws[ch & 1];
#pragma unroll
            for (int jj = 0; jj < 8; jj++) {
                int j = ch * 8 + jj;
                const ull* hpj = &S->hp[j * 18 + kh * 8];
                ulonglong2 hq0 = *(const ulonglong2*)&hpj[0];
                ulonglong2 hq1 = *(const ulonglong2*)&hpj[2];
                ulonglong2 hq2 = *(const ulonglong2*)&hpj[4];
                ulonglong2 hq3 = *(const ulonglong2*)&hpj[6];
                float2 wv = *(const float2*)&wsb[jj * 256 + cg * 64 + d0l];
                ull w0 = pk(wv.x, wv.x);
                ull w1 = pk(wv.y, wv.y);
                fma2(acc[0][0], hq0.x, w0); fma2(acc[0][1], hq0.x, w1);
                fma2(acc[1][0], hq0.y, w0); fma2(acc[1][1], hq0.y, w1);
                fma2(acc[2][0], hq1.x, w0); fma2(acc[2][1], hq1.x, w1);
                fma2(acc[3][0], hq1.y, w0); fma2(acc[3][1], hq1.y, w1);
                fma2(acc[4][0], hq2.x, w0); fma2(acc[4][1], hq2.x, w1);
                fma2(acc[5][0], hq2.y, w0); fma2(acc[5][1], hq2.y, w1);
                fma2(acc[6][0], hq3.x, w0); fma2(acc[6][1], hq3.x, w1);
                fma2(acc[7][0], hq3.y, w0); fma2(acc[7][1], hq3.y, w1);
            }
        }
        __syncthreads();   // ALL pairs done with ws/hp before G alias store

        // store G in gathered k order (aliases ws + low hp; all reads done)
#pragma unroll
        for (int kp = 0; kp < 8; kp++) {
            int k0 = kh * 16 + kp * 2;
            int cc = cg * 64 + d0l;
            float2 v0 = unpk(acc[kp][0]);
            float2 v1 = unpk(acc[kp][1]);
            Gs[k0 * 256 + cc]           = v0.x;
            Gs[(k0 + 1) * 256 + cc]     = v0.y;
            Gs[k0 * 256 + cc + 1]       = v1.x;
            Gs[(k0 + 1) * 256 + cc + 1] = v1.y;
        }
        // no sync here: merged with the post-spin sync below
    }

    // hoist epilogue weight loads above the spin (independent of yt/sp)
    float wih[8], bsum[8];
#pragma unroll
    for (int g4 = 0; g4 < 4; g4++)
#pragma unroll
        for (int dd = 0; dd < 2; dd++) {
            int col = g4 * 128 + d0g + dd;
            wih[g4 * 2 + dd]  = Wih[col];
            bsum[g4 * 2 + dd] = bih[col] + bhh[col];
        }
    float fcd0 = fcdW[d0g], fcd1 = fcdW[d0g + 1];
    float pw0 = pdfW[d0g],  pw1 = pdfW[d0g + 1];

    // wait for attention (yt, sp); sync also publishes the G stores CTA-wide
    if (tid == 0) spin_ge(&g_attnFlag[b], (unsigned)(t + 1));
    __syncthreads();

    // ---- epilogue: warps remap to distinct k (wid*4..wid*4+3) ----
    float yt = g_yt[b];
    float2 spv = *(const float2*)&g_spF[b * 128 + d0g];
    float xb[8];
#pragma unroll
    for (int c = 0; c < 8; c++) xb[c] = yt * wih[c] + bsum[c];

    float pacc[4], qacc[4];
#pragma unroll
    for (int i = 0; i < 4; i++) {
        int k = wid * 4 + i;
        ull gv[4] = {0ull, 0ull, 0ull, 0ull};
        float cp0 = 0.0f, cp1 = 0.0f;
        if (t > 0) {
#pragma unroll
            for (int g = 0; g < 4; g++)
                gv[g] = *(const ull*)&Gs[k * 256 + g * 64 + d0l];
            int crow = g_srcC[k * BB + b];
            float2 cv = *(const float2*)&g_C[rb][(crow * BB + b) * DH + d0g];
            cp0 = cv.x; cp1 = cv.y;
        }
        float2 gi = unpk(gv[0]);
        float2 gf = unpk(gv[1]);
        float2 gg = unpk(gv[2]);
        float2 go = unpk(gv[3]);
        float ii0 = gi.x + xb[0], ii1 = gi.y + xb[1];
        float ff0 = gf.x + xb[2], ff1 = gf.y + xb[3];
        float gg0 = gg.x + xb[4], gg1 = gg.y + xb[5];
        float oo0 = go.x + xb[6], oo1 = go.y + xb[7];
        float c20 = sigm(ff0) * cp0 + sigm(ii0) * tanhf(gg0);
        float c21 = sigm(ff1) * cp1 + sigm(ii1) * tanhf(gg1);
        float h20 = sigm(oo0) * tanhf(c20);
        float h21 = sigm(oo1) * tanhf(c21);
        float2 ev = *(const float2*)&eps[(((size_t)t * KP + k) * BB + b) * DH + d0g];
        h20 += ev.x * spv.x;
        h21 += ev.y * spv.y;
        int o = (k * BB + b) * DH + d0g;
        *(float2*)&g_H[wb][o] = make_float2(h20, h21);
        *(float2*)&g_C[wb][o] = make_float2(c20, c21);
        pacc[i] = h20 * fcd0 + h21 * fcd1;
        qacc[i] = h20 * pw0 + h21 * pw1;
    }
#pragma unroll
    for (int i = 0; i < 4; i++) {
        float p = pacc[i], q = qacc[i];
        for (int off = 16; off; off >>= 1) {
            p += __shfl_down_sync(0xffffffffu, p, off);
            q += __shfl_down_sync(0xffffffffu, q, off);
        }
        if (lane == 0) {
            int k = wid * 4 + i;
            g_projP[dh][k * BB + b] = p;
            g_pdfP[dh][k * BB + b] = q;
        }
    }
}

// ---------------- K3: sort / weights / gumbel-max resample ----------------
__global__ void __launch_bounds__(1024) k3_resample(
        int t, const float* __restrict__ gumbel,
        const float* __restrict__ pdfW, const float* __restrict__ pdfb,
        const float* __restrict__ fcdb)
{
    int blk = blockIdx.x;
    int tid = threadIdx.x;
    __shared__ float proj_s[32][33];
    __shared__ int   order_s[32][33];
    __shared__ float pd_s[32][33];
    __shared__ float lw_s[32][33];

    {
        int kk = tid >> 5, bb = tid & 31;
        int gi = kk * BB + blk * 32 + bb;
        proj_s[bb][kk] = g_projP[0][gi] + g_projP[1][gi] + fcdb[0];
        pd_s[bb][kk]   = g_pdfP[0][gi] + g_pdfP[1][gi];
    }
    __syncthreads();
    {
        int bl = tid >> 5, k = tid & 31;
        float v = proj_s[bl][k];
        int r = 0;
#pragma unroll
        for (int kp = 0; kp < 32; kp++) {
            float u = proj_s[bl][kp];
            r += (u < v) || (u == v && kp < k);
        }
        order_s[bl][r] = k;
    }
    __syncthreads();
    {
        int slot = tid >> 5, bb = tid & 31;
        int bg = blk * 32 + bb;
        int k0 = order_s[bb][slot];
        float lp = pd_s[bb][k0] + g_yt[bg] * pdfW[128] + pdfb[0];
        float v = expf(lp);
        float s = v;
        for (int off = 16; off; off >>= 1) s += __shfl_xor_sync(0xffffffffu, s, off);
        lw_s[bb][slot] = logf(v / s + 1e-30f);
    }
    __syncthreads();
    {
        int p = tid >> 5, lane = tid & 31;
        const float* gbase = &gumbel[(((size_t)t * BB + blk * 32) * KP + p) * KP + lane];
        float gv[32];
#pragma unroll
        for (int it = 0; it < 32; it++)
            gv[it] = gbase[(size_t)it * KP * KP];
#pragma unroll
        for (int it = 0; it < 32; it++) {
            float v = lw_s[it][lane] + gv[it];
            int bi = lane;
            for (int off = 16; off; off >>= 1) {
                float ov = __shfl_down_sync(0xffffffffu, v, off);
                int  obi = __shfl_down_sync(0xffffffffu, bi, off);
                if (ov > v || (ov == v && obi < bi)) { v = ov; bi = obi; }
            }
            if (lane == 0) {
                int bg = blk * 32 + it;
                g_srcH[p * BB + bg] = order_s[it][bi];
                g_srcC[p * BB + bg] = bi;
            }
        }
    }
}

// ---------------- K4: final projections -----------------------------------
__global__ void k4_out(const float* __restrict__ fcdW, const float* __restrict__ fcdb,
                       const float* __restrict__ fceW, const float* __restrict__ fceb,
                       float* __restrict__ out)
{
    int b = blockIdx.x * 8 + (threadIdx.x >> 5);
    int lane = threadIdx.x & 31;
    float a1 = 0.0f, a2 = 0.0f;
    for (int d = lane; d < 128; d += 32) {
        float hm = 0.0f;
        for (int p = 0; p < KP; p++) {
            int row = g_srcH[p * BB + b];
            hm += g_H[1][(row * BB + b) * DH + d];   // (T-1)&1 == 1
        }
        a1 += (hm * (1.0f / 32.0f)) * fcdW[d];
        a2 += g_ctx[b * 128 + d] * fceW[d];
    }
    for (int off = 16; off; off >>= 1) {
        a1 += __shfl_down_sync(0xffffffffu, a1, off);
        a2 += __shfl_down_sync(0xffffffffu, a2, off);
    }
    if (lane == 0) out[b] = a1 + fcdb[0] + a2 + fceb[0];
}

// ---------------- launch ---------------------------------------------------
extern "C" void kernel_launch(void* const* d_in, const int* in_sizes, int n_in,
                              void* d_out, int out_size)
{
    const float* enc   = (const float*)d_in[0];
    const float* yprev = (const float*)d_in[1];
    const float* eps   = (const float*)d_in[2];
    const float* gum   = (const float*)d_in[3];
    const float* W1    = (const float*)d_in[4];
    const float* b1    = (const float*)d_in[5];
    const float* W2    = (const float*)d_in[6];
    const float* b2    = (const float*)d_in[7];
    const float* Wih   = (const float*)d_in[8];
    const float* Whh   = (const float*)d_in[9];
    const float* bih   = (const float*)d_in[10];
    const float* bhh   = (const float*)d_in[11];
    const float* fcW   = (const float*)d_in[12];
    const float* fcb   = (const float*)d_in[13];
    const float* fcdW  = (const float*)d_in[14];
    const float* fcdb  = (const float*)d_in[15];
    const float* fceW  = (const float*)d_in[16];
    const float* fceb  = (const float*)d_in[17];
    const float* varW  = (const float*)d_in[18];
    const float* varb  = (const float*)d_in[19];
    const float* pdfW  = (const float*)d_in[20];
    const float* pdfb  = (const float*)d_in[21];
    float* out = (float*)d_out;

    int smem = (int)sizeof(SmemG);
    if ((int)sizeof(SmemT) > smem) smem = (int)sizeof(SmemT);
    if (smem < 32 * 256 * 4) smem = 32 * 256 * 4;   // G alias needs 32 KB
    cudaFuncSetAttribute(kStep, cudaFuncAttributeMaxDynamicSharedMemorySize, smem);

    k0_e1<<<BB * 2, 256>>>(enc, W1, b1);
    for (int t = 0; t < TT; t++) {
        kStep<<<64 + BB * 2, 256, smem>>>(t, enc, yprev, W1, W2, b2, fcW, fcb,
                                          varW, varb, Whh, Wih, bih, bhh, eps,
                                          fcdW, pdfW);
        k3_resample<<<8, 1024>>>(t, gum, pdfW, pdfb, fcdb);
    }
    k4_out<<<BB / 8, 256>>>(fcdW, fcdb, fceW, fceb, out);
}